// round 13
// baseline (speedup 1.0000x reference)
#include <cuda_runtime.h>
#include <stdint.h>

#define B    16
#define N    8192
#define P    1024
#define C    256
#define K    64
#define OUTC (3 + C)   // 259
#define CPB  4         // channels per block in group_feat

// Scratch for ball-query indices: [B, P, K] int16 = 2 MB (N=8192 fits short)
__device__ short g_idx[B * P * K];

// ---------------------------------------------------------------------------
// Kernel 1: ball query. 256 blocks (16 per batch), 1024 threads (32 warps),
// 104 KB smem -> 2 CTAs/SM (64 warps/SM). xyz[b] staged as 3 scalar floats;
// warps pull centers (64/block) from a per-block atomic work queue; scan
// processes 128 points per iteration (4 batched ballots).
// Arithmetic (validated in R4, bit-matches reference):
//   ssq tree : (x^2 + z^2) + y^2, separately-rounded muls
//   dot      : fma(cz,z, fma(cy,y, rn(cx*x)))
//   d2       : (cc + xx) - 2*dot
// Selection: first K ascending indices with d2 < r^2; empty slots filled
// with first found index (0 if none).
// ---------------------------------------------------------------------------
__global__ __launch_bounds__(1024, 2) void ball_query_kernel(
    const float* __restrict__ xyz,      // [B, N, 3]
    const float* __restrict__ new_xyz,  // [B, P, 3]
    float* __restrict__ out)            // [B, OUTC, P, K]
{
    const float R2 = (float)(0.3 * 0.3);

    extern __shared__ float smem[];
    float* sxyz   = smem;                     // [3*N] = 96 KB
    int*   s_idx  = (int*)(smem + 3 * N);     // [32][K] = 8 KB
    int*   s_next = (int*)(smem + 3 * N + 32 * K);  // work queue counter

    int tid  = threadIdx.x;
    int lane = tid & 31;
    int wid  = tid >> 5;                     // 0..31
    int b    = blockIdx.x >> 4;              // 16 blocks per batch
    int pgrp = (blockIdx.x & 15) * 64;       // this block's 64 centers

    if (tid == 0) *s_next = 0;

    // Stage xyz[b] into smem (coalesced float4)
    const float4* src = (const float4*)(xyz + (size_t)b * N * 3);
    #pragma unroll
    for (int i = tid; i < 3 * N / 4; i += 1024)
        ((float4*)sxyz)[i] = src[i];
    __syncthreads();

    unsigned lmask = (1u << lane) - 1u;
    int* myidx = s_idx + wid * K;

    for (;;) {
        int ci = 0;
        if (lane == 0) ci = atomicAdd(s_next, 1);
        ci = __shfl_sync(0xffffffffu, ci, 0);
        if (ci >= 64) break;
        int p = pgrp + ci;

        const float* ctr = new_xyz + ((size_t)b * P + p) * 3;
        float cx = ctr[0], cy = ctr[1], cz = ctr[2];
        float cc = __fadd_rn(__fadd_rn(__fmul_rn(cx, cx), __fmul_rn(cz, cz)),
                             __fmul_rn(cy, cy));

        int count = 0;
        for (int base = 0; base < N; base += 128) {
            unsigned msk[4];
            int cnt[4];
            #pragma unroll
            for (int g = 0; g < 4; g++) {
                int n = base + g * 32 + lane;
                float x = sxyz[n * 3 + 0];
                float y = sxyz[n * 3 + 1];
                float z = sxyz[n * 3 + 2];
                float xx  = __fadd_rn(__fadd_rn(__fmul_rn(x, x), __fmul_rn(z, z)),
                                      __fmul_rn(y, y));
                float dot = __fmaf_rn(cz, z, __fmaf_rn(cy, y, __fmul_rn(cx, x)));
                float d2  = __fsub_rn(__fadd_rn(cc, xx), __fmul_rn(2.0f, dot));
                msk[g] = __ballot_sync(0xffffffffu, d2 < R2);
                cnt[g] = __popc(msk[g]);
            }
            int run = count;
            #pragma unroll
            for (int g = 0; g < 4; g++) {
                int n = base + g * 32 + lane;
                bool in = (msk[g] >> lane) & 1u;
                int pos = run + __popc(msk[g] & lmask);
                if (in && pos < K) myidx[pos] = n;
                run += cnt[g];
            }
            count = run;
            if (count >= K) break;
        }
        if (count > K) count = K;
        __syncwarp();

        int first = (count == 0) ? 0 : myidx[0];
        for (int k = count + lane; k < K; k += 32) myidx[k] = first;
        __syncwarp();

        short* gidx = g_idx + ((size_t)b * P + p) * K;
        size_t obase = (((size_t)b * OUTC) * P + p) * K;
        #pragma unroll
        for (int t = 0; t < 2; t++) {
            int k = lane + t * 32;
            int n = myidx[k];
            gidx[k] = (short)n;
            float gx = __fdiv_rn(__fsub_rn(sxyz[n * 3 + 0], cx), 0.3f);
            float gy = __fdiv_rn(__fsub_rn(sxyz[n * 3 + 1], cy), 0.3f);
            float gz = __fdiv_rn(__fsub_rn(sxyz[n * 3 + 2], cz), 0.3f);
            __stcs(&out[obase + 0 * (size_t)P * K + k], gx);
            __stcs(&out[obase + 1 * (size_t)P * K + k], gy);
            __stcs(&out[obase + 2 * (size_t)P * K + k], gz);
        }
        __syncwarp();
    }
}

// ---------------------------------------------------------------------------
// Kernel 2: feature grouping, 4 channels per block, 1024 threads (validated:
// 182.5us, DRAM 79.5%). Interleaved float4 smem image; one LDS.128 per
// gathered point serves 4 output channels. int16 idx stream, software-
// pipelined one iteration ahead. Streaming stores.
// ---------------------------------------------------------------------------
__global__ __launch_bounds__(1024, 1) void group_feat_kernel(
    const float* __restrict__ feat,   // [B, C, N]
    float* __restrict__ out)          // [B, OUTC, P, K]
{
    extern __shared__ float4 srow[];  // [N] = 128 KB

    int b  = blockIdx.x >> 6;            // / (C/CPB)
    int cq = blockIdx.x & 63;            // channel quad
    int c0 = cq * CPB;

    const float* r0 = feat + (((size_t)b * C + c0 + 0) * N);
    const float* r1 = feat + (((size_t)b * C + c0 + 1) * N);
    const float* r2 = feat + (((size_t)b * C + c0 + 2) * N);
    const float* r3 = feat + (((size_t)b * C + c0 + 3) * N);

    #pragma unroll
    for (int n = threadIdx.x; n < N; n += 1024) {
        float4 v;
        v.x = r0[n]; v.y = r1[n]; v.z = r2[n]; v.w = r3[n];
        srow[n] = v;   // conflict-free STS.128 (consecutive n)
    }
    __syncthreads();

    const short4* idx4 = (const short4*)g_idx + (size_t)b * (P * K / 4);
    size_t ob = ((size_t)b * OUTC + 3 + c0) * P * K;
    float4* d0 = (float4*)(out + ob + 0 * (size_t)P * K);
    float4* d1 = (float4*)(out + ob + 1 * (size_t)P * K);
    float4* d2 = (float4*)(out + ob + 2 * (size_t)P * K);
    float4* d3 = (float4*)(out + ob + 3 * (size_t)P * K);

    const int NI = P * K / 4;            // 16384; 16 iterations per thread
    int i = threadIdx.x;
    short4 v = idx4[i];
    #pragma unroll 4
    while (i < NI) {
        int inext = i + 1024;
        short4 vn;
        if (inext < NI) vn = idx4[inext];   // prefetch next iteration's idx
        float4 a  = srow[v.x];
        float4 bb = srow[v.y];
        float4 cc = srow[v.z];
        float4 dd = srow[v.w];
        __stcs(&d0[i], make_float4(a.x, bb.x, cc.x, dd.x));
        __stcs(&d1[i], make_float4(a.y, bb.y, cc.y, dd.y));
        __stcs(&d2[i], make_float4(a.z, bb.z, cc.z, dd.z));
        __stcs(&d3[i], make_float4(a.w, bb.w, cc.w, dd.w));
        v = vn;
        i = inext;
    }
}

extern "C" void kernel_launch(void* const* d_in, const int* in_sizes, int n_in,
                              void* d_out, int out_size)
{
    (void)in_sizes; (void)n_in; (void)out_size;
    const float* xyz     = (const float*)d_in[0];   // [16, 8192, 3]
    const float* new_xyz = (const float*)d_in[1];   // [16, 1024, 3]
    const float* feat    = (const float*)d_in[2];   // [16, 256, 8192]
    float* out = (float*)d_out;                     // [16, 259, 1024, 64]

    const int bq_smem = 3 * N * sizeof(float) + 32 * K * sizeof(int) + 16; // 104 KB
    const int gf_smem = N * sizeof(float4);                                // 128 KB
    cudaFuncSetAttribute(ball_query_kernel,
                         cudaFuncAttributeMaxDynamicSharedMemorySize, bq_smem);
    cudaFuncSetAttribute(group_feat_kernel,
                         cudaFuncAttributeMaxDynamicSharedMemorySize, gf_smem);

    ball_query_kernel<<<256, 1024, bq_smem>>>(xyz, new_xyz, out);
    group_feat_kernel<<<B * (C / CPB), 1024, gf_smem>>>(feat, out);
}

// round 14
// speedup vs baseline: 1.0573x; 1.0573x over previous
#include <cuda_runtime.h>
#include <stdint.h>

#define B    16
#define N    8192
#define P    1024
#define C    256
#define K    64
#define OUTC (3 + C)   // 259
#define CPB  4         // channels per block in group_feat

#define BQ_BPB  9                      // bq blocks per batch
#define BQ_CPB  ((P + BQ_BPB - 1) / BQ_BPB)   // 114 centers per block

// Scratch for ball-query indices: [B, P, K] int16 = 2 MB (N=8192 fits short)
__device__ short g_idx[B * P * K];

// ---------------------------------------------------------------------------
// Kernel 1: ball query. 144 blocks (9 per batch, ~114 centers each; 4 idle
// SMs instead of 20), 1024 threads, 1 CTA/SM. Points staged in smem as
// float4 (x, y, z, xx), xx = (x^2+z^2)+y^2 precomputed once per point with
// the exact validated rn-op sequence (value-identical hoist). Inner scan:
// 1 LDS.128 per point + fma dot; warps pull centers from a per-block atomic
// work queue; 128 points per iteration (4 batched ballots).
// Arithmetic (validated in R4, bit-matches reference):
//   ssq tree : (x^2 + z^2) + y^2, separately-rounded muls
//   dot      : fma(cz,z, fma(cy,y, rn(cx*x)))
//   d2       : (cc + xx) - 2*dot
// Selection: first K ascending indices with d2 < r^2; empty slots filled
// with first found index (0 if none).
// ---------------------------------------------------------------------------
__global__ __launch_bounds__(1024, 1) void ball_query_kernel(
    const float* __restrict__ xyz,      // [B, N, 3]
    const float* __restrict__ new_xyz,  // [B, P, 3]
    float* __restrict__ out)            // [B, OUTC, P, K]
{
    const float R2 = (float)(0.3 * 0.3);

    extern __shared__ float smem[];
    float4* spts  = (float4*)smem;                  // [N] = 128 KB
    int*    s_idx = (int*)(smem + 4 * N);           // [32][K] = 8 KB
    int*    s_next = (int*)(smem + 4 * N + 32 * K); // work queue counter

    int tid  = threadIdx.x;
    int lane = tid & 31;
    int wid  = tid >> 5;                     // 0..31
    int b    = blockIdx.x / BQ_BPB;
    int sub  = blockIdx.x - b * BQ_BPB;
    int pstart = sub * BQ_CPB;
    int pend   = pstart + BQ_CPB;
    if (pend > P) pend = P;
    int nwork = pend - pstart;

    if (tid == 0) *s_next = 0;

    // Stage xyz[b] into smem as (x, y, z, xx); xx via the validated rn tree
    const float* pts = xyz + (size_t)b * N * 3;
    #pragma unroll
    for (int n = tid; n < N; n += 1024) {
        float x = pts[n * 3 + 0];
        float y = pts[n * 3 + 1];
        float z = pts[n * 3 + 2];
        float xx = __fadd_rn(__fadd_rn(__fmul_rn(x, x), __fmul_rn(z, z)),
                             __fmul_rn(y, y));
        spts[n] = make_float4(x, y, z, xx);
    }
    __syncthreads();

    unsigned lmask = (1u << lane) - 1u;
    int* myidx = s_idx + wid * K;

    for (;;) {
        int ci = 0;
        if (lane == 0) ci = atomicAdd(s_next, 1);
        ci = __shfl_sync(0xffffffffu, ci, 0);
        if (ci >= nwork) break;
        int p = pstart + ci;

        const float* ctr = new_xyz + ((size_t)b * P + p) * 3;
        float cx = ctr[0], cy = ctr[1], cz = ctr[2];
        float cc = __fadd_rn(__fadd_rn(__fmul_rn(cx, cx), __fmul_rn(cz, cz)),
                             __fmul_rn(cy, cy));

        int count = 0;
        for (int base = 0; base < N; base += 128) {
            unsigned msk[4];
            int cnt[4];
            #pragma unroll
            for (int g = 0; g < 4; g++) {
                int n = base + g * 32 + lane;
                float4 q = spts[n];
                float dot = __fmaf_rn(cz, q.z, __fmaf_rn(cy, q.y, __fmul_rn(cx, q.x)));
                float d2  = __fsub_rn(__fadd_rn(cc, q.w), __fmul_rn(2.0f, dot));
                msk[g] = __ballot_sync(0xffffffffu, d2 < R2);
                cnt[g] = __popc(msk[g]);
            }
            int run = count;
            #pragma unroll
            for (int g = 0; g < 4; g++) {
                int n = base + g * 32 + lane;
                bool in = (msk[g] >> lane) & 1u;
                int pos = run + __popc(msk[g] & lmask);
                if (in && pos < K) myidx[pos] = n;
                run += cnt[g];
            }
            count = run;
            if (count >= K) break;
        }
        if (count > K) count = K;
        __syncwarp();

        int first = (count == 0) ? 0 : myidx[0];
        for (int k = count + lane; k < K; k += 32) myidx[k] = first;
        __syncwarp();

        short* gidx = g_idx + ((size_t)b * P + p) * K;
        size_t obase = (((size_t)b * OUTC) * P + p) * K;
        #pragma unroll
        for (int t = 0; t < 2; t++) {
            int k = lane + t * 32;
            int n = myidx[k];
            gidx[k] = (short)n;
            float4 q = spts[n];
            float gx = __fdiv_rn(__fsub_rn(q.x, cx), 0.3f);
            float gy = __fdiv_rn(__fsub_rn(q.y, cy), 0.3f);
            float gz = __fdiv_rn(__fsub_rn(q.z, cz), 0.3f);
            out[obase + 0 * (size_t)P * K + k] = gx;
            out[obase + 1 * (size_t)P * K + k] = gy;
            out[obase + 2 * (size_t)P * K + k] = gz;
        }
        __syncwarp();
    }
}

// ---------------------------------------------------------------------------
// Kernel 2: feature grouping, 4 channels per block, 1024 threads (validated
// R11/R12: 182.5us, DRAM 79.5%). Interleaved float4 smem image; one LDS.128
// per gathered point serves 4 output channels. int16 idx stream, software-
// pipelined one iteration ahead. Streaming stores.
// ---------------------------------------------------------------------------
__global__ __launch_bounds__(1024, 1) void group_feat_kernel(
    const float* __restrict__ feat,   // [B, C, N]
    float* __restrict__ out)          // [B, OUTC, P, K]
{
    extern __shared__ float4 srow[];  // [N] = 128 KB

    int b  = blockIdx.x >> 6;            // / (C/CPB)
    int cq = blockIdx.x & 63;            // channel quad
    int c0 = cq * CPB;

    const float* r0 = feat + (((size_t)b * C + c0 + 0) * N);
    const float* r1 = feat + (((size_t)b * C + c0 + 1) * N);
    const float* r2 = feat + (((size_t)b * C + c0 + 2) * N);
    const float* r3 = feat + (((size_t)b * C + c0 + 3) * N);

    #pragma unroll
    for (int n = threadIdx.x; n < N; n += 1024) {
        float4 v;
        v.x = r0[n]; v.y = r1[n]; v.z = r2[n]; v.w = r3[n];
        srow[n] = v;   // conflict-free STS.128 (consecutive n)
    }
    __syncthreads();

    const short4* idx4 = (const short4*)g_idx + (size_t)b * (P * K / 4);
    size_t ob = ((size_t)b * OUTC + 3 + c0) * P * K;
    float4* d0 = (float4*)(out + ob + 0 * (size_t)P * K);
    float4* d1 = (float4*)(out + ob + 1 * (size_t)P * K);
    float4* d2 = (float4*)(out + ob + 2 * (size_t)P * K);
    float4* d3 = (float4*)(out + ob + 3 * (size_t)P * K);

    const int NI = P * K / 4;            // 16384; 16 iterations per thread
    int i = threadIdx.x;
    short4 v = idx4[i];
    #pragma unroll 4
    while (i < NI) {
        int inext = i + 1024;
        short4 vn;
        if (inext < NI) vn = idx4[inext];   // prefetch next iteration's idx
        float4 a  = srow[v.x];
        float4 bb = srow[v.y];
        float4 cc = srow[v.z];
        float4 dd = srow[v.w];
        __stcs(&d0[i], make_float4(a.x, bb.x, cc.x, dd.x));
        __stcs(&d1[i], make_float4(a.y, bb.y, cc.y, dd.y));
        __stcs(&d2[i], make_float4(a.z, bb.z, cc.z, dd.z));
        __stcs(&d3[i], make_float4(a.w, bb.w, cc.w, dd.w));
        v = vn;
        i = inext;
    }
}

extern "C" void kernel_launch(void* const* d_in, const int* in_sizes, int n_in,
                              void* d_out, int out_size)
{
    (void)in_sizes; (void)n_in; (void)out_size;
    const float* xyz     = (const float*)d_in[0];   // [16, 8192, 3]
    const float* new_xyz = (const float*)d_in[1];   // [16, 1024, 3]
    const float* feat    = (const float*)d_in[2];   // [16, 256, 8192]
    float* out = (float*)d_out;                     // [16, 259, 1024, 64]

    const int bq_smem = 4 * N * sizeof(float) + 32 * K * sizeof(int) + 16; // 136 KB
    const int gf_smem = N * sizeof(float4);                                // 128 KB
    cudaFuncSetAttribute(ball_query_kernel,
                         cudaFuncAttributeMaxDynamicSharedMemorySize, bq_smem);
    cudaFuncSetAttribute(group_feat_kernel,
                         cudaFuncAttributeMaxDynamicSharedMemorySize, gf_smem);

    ball_query_kernel<<<B * BQ_BPB, 1024, bq_smem>>>(xyz, new_xyz, out);
    group_feat_kernel<<<B * (C / CPB), 1024, gf_smem>>>(feat, out);
}